// round 6
// baseline (speedup 1.0000x reference)
#include <cuda_runtime.h>
#include <cuda_bf16.h>
#include <cstdint>

#define NROWS  8192
#define DIM    512
#define KCODES 16384
#define CAP    64
#define MARGIN 4e-4f

// Filter-kernel geometry
#define ROWT      128                 // rows per CTA
#define AS_STRIDE 1040u               // bytes per A smem row (520 halves)
#define AS_BYTES  (128u * AS_STRIDE)  // 133120
#define BS_STRIDE 144u                // bytes per B smem row (72 halves)
#define BBUF      (128u * BS_STRIDE)  // 18432 per buffer
#define C2_OFF    (AS_BYTES + 2u * BBUF)          // 169984
#define SMEM_TOT  (C2_OFF + 512u)                 // 170496

// ---------------- device-global scratch (no runtime allocation) -------------
__device__ __nv_bfloat16 g_abf[NROWS * DIM];     // 8 MB
__device__ __nv_bfloat16 g_bbf[KCODES * DIM];    // 16 MB
__device__ float  g_c2[KCODES];
__device__ float  g_x2[NROWS];
__device__ int    g_cand_cnt[NROWS];
__device__ int    g_cand[NROWS * CAP];
__device__ int    g_idx[NROWS];
__device__ double g_loss;

// ---------------- PTX helpers ----------------------------------------------
static __device__ __forceinline__ uint32_t sptr(const void* p) {
    return (uint32_t)__cvta_generic_to_shared(p);
}
#define CP_ASYNC16(dst, src) \
    asm volatile("cp.async.cg.shared.global [%0], [%1], 16;" :: "r"(dst), "l"(src))
#define CP_COMMIT() asm volatile("cp.async.commit_group;")
#define CP_WAIT(n)  asm volatile("cp.async.wait_group %0;" :: "n"(n))

#define LDSM_X4(r0, r1, r2, r3, addr) \
    asm volatile("ldmatrix.sync.aligned.m8n8.x4.shared.b16 {%0,%1,%2,%3}, [%4];" \
        : "=r"(r0), "=r"(r1), "=r"(r2), "=r"(r3) : "r"(addr))
#define LDSM_X2(r0, r1, addr) \
    asm volatile("ldmatrix.sync.aligned.m8n8.x2.shared.b16 {%0,%1}, [%2];" \
        : "=r"(r0), "=r"(r1) : "r"(addr))
#define MMA16816(C, A, B) \
    asm volatile("mma.sync.aligned.m16n8k16.row.col.f32.bf16.bf16.f32 " \
        "{%0,%1,%2,%3}, {%4,%5,%6,%7}, {%8,%9}, {%0,%1,%2,%3};" \
        : "+f"((C)[0]), "+f"((C)[1]), "+f"((C)[2]), "+f"((C)[3]) \
        : "r"((A)[0]), "r"((A)[1]), "r"((A)[2]), "r"((A)[3]), "r"((B)[0]), "r"((B)[1]))

// ---------------------------------------------------------------------------
__global__ void convert_kernel(const float* __restrict__ in,
                               __nv_bfloat16* __restrict__ out, int total) {
    int idx = blockIdx.x * blockDim.x + threadIdx.x;
    if (idx < total) out[idx] = __float2bfloat16(in[idx]);
}

// ---------------------------------------------------------------------------
__global__ void c2_kernel(const float* __restrict__ cb) {
    const int row  = blockIdx.x * 8 + (threadIdx.x >> 5);
    const int lane = threadIdx.x & 31;
    const float4* p = reinterpret_cast<const float4*>(cb + (size_t)row * DIM);
    float s = 0.f;
#pragma unroll
    for (int q = 0; q < 4; q++) {
        float4 v = p[lane + 32 * q];
        s += v.x * v.x + v.y * v.y + v.z * v.z + v.w * v.w;
    }
#pragma unroll
    for (int o = 16; o; o >>= 1) s += __shfl_xor_sync(0xFFFFFFFFu, s, o);
    if (lane == 0) g_c2[row] = s;
}

// x2 strict sequential fp32 (reference rounding order); zeroes loss+counters
__global__ void x2_kernel(const float* __restrict__ x) {
    const int row = blockIdx.x * blockDim.x + threadIdx.x;
    if (row == 0) g_loss = 0.0;
    if (row >= NROWS) return;
    g_cand_cnt[row] = 0;
    const float4* p = reinterpret_cast<const float4*>(x + (size_t)row * DIM);
    float acc = 0.f;
#pragma unroll 8
    for (int i = 0; i < DIM / 4; i++) {
        float4 v = __ldg(p + i);
        acc = __fadd_rn(acc, __fmul_rn(v.x, v.x));
        acc = __fadd_rn(acc, __fmul_rn(v.y, v.y));
        acc = __fadd_rn(acc, __fmul_rn(v.z, v.z));
        acc = __fadd_rn(acc, __fmul_rn(v.w, v.w));
    }
    g_x2[row] = acc;
}

// ---------------------------------------------------------------------------
// bf16 HMMA filter: approximate distances + running-min candidate collection.
// A (128 rows x 512 k) resident in smem; B streamed 128x64 double-buffered.
__global__ __launch_bounds__(256, 1)
void filter_kernel() {
    extern __shared__ char smem[];
    const uint32_t As = sptr(smem);
    const uint32_t Bs = As + AS_BYTES;
    float* c2p = reinterpret_cast<float*>(smem + C2_OFF);

    const int tid    = threadIdx.x;
    const int lane   = tid & 31;
    const int wid    = tid >> 5;
    const int warp_m = wid >> 2;          // 0..1  (64 rows each)
    const int warp_n = wid & 3;           // 0..3  (32 codes each)
    const int rt     = blockIdx.x * ROWT;
    const int half   = blockIdx.y;        // 0..1
    const int g      = lane >> 2;         // group 0..7
    const int t4     = lane & 3;

    // ldmatrix lane address bases
    const int lr   = lane & 7;
    const int lsel = lane >> 3;                       // 0..3
    const uint32_t a_base = As + (uint32_t)(warp_m * 64 + (lsel & 1) * 8 + lr) * AS_STRIDE
                               + (uint32_t)((lsel >> 1) * 8) * 2u;
    const uint32_t b_base = Bs + (uint32_t)(warp_n * 32 + lr) * BS_STRIDE
                               + (uint32_t)((lsel & 1) * 8) * 2u;

    // Resident A load (one cp.async group)
    {
        const __nv_bfloat16* asrc = g_abf + (size_t)rt * DIM;
        for (int i = tid; i < 8192; i += 256) {
            int row = i >> 6, ch = i & 63;
            CP_ASYNC16(As + (uint32_t)row * AS_STRIDE + (uint32_t)ch * 16u,
                       asrc + (size_t)row * DIM + ch * 8);
        }
        CP_COMMIT();
        CP_WAIT(0);
        __syncthreads();
    }

    // per-lane row metadata (8 rows: mt 0..3 x h 0..1)
    int   grow[8];
    float x2v[8];
    float runmin[8];
#pragma unroll
    for (int mt = 0; mt < 4; mt++)
#pragma unroll
        for (int h = 0; h < 2; h++) {
            int ri = mt * 2 + h;
            grow[ri] = rt + warp_m * 64 + mt * 16 + h * 8 + g;
            x2v[ri]  = g_x2[grow[ri]];
            runmin[ri] = 3.4e38f;
        }

    for (int ct = 0; ct < 64; ct++) {
        const int code0 = half * 8192 + ct * 128;

        // issue B chunks kc=0,1
#pragma unroll
        for (int kc = 0; kc < 2; kc++) {
            const __nv_bfloat16* bsrc = g_bbf + (size_t)code0 * DIM + kc * 64;
#pragma unroll
            for (int u = 0; u < 4; u++) {
                int i = tid + u * 256;
                int code = i >> 3, ch = i & 7;
                CP_ASYNC16(Bs + (uint32_t)kc * BBUF + (uint32_t)code * BS_STRIDE + (uint32_t)ch * 16u,
                           bsrc + (size_t)code * DIM + ch * 8);
            }
            CP_COMMIT();
        }
        __syncthreads();   // prior epilogue done reading c2p
        if (tid < 128) c2p[tid] = g_c2[code0 + tid];

        float C[4][4][4];
#pragma unroll
        for (int mt = 0; mt < 4; mt++)
#pragma unroll
            for (int nt = 0; nt < 4; nt++)
#pragma unroll
                for (int e = 0; e < 4; e++) C[mt][nt][e] = 0.f;

        for (int kc = 0; kc < 8; kc++) {
            if (kc < 7) { CP_WAIT(1); } else { CP_WAIT(0); }
            __syncthreads();
            const uint32_t bb = b_base + (uint32_t)(kc & 1) * BBUF;
#pragma unroll
            for (int k16 = 0; k16 < 4; k16++) {
                const uint32_t ka = (uint32_t)(kc * 64 + k16 * 16) * 2u;
                uint32_t a[4][4], b[4][2];
#pragma unroll
                for (int mt = 0; mt < 4; mt++)
                    LDSM_X4(a[mt][0], a[mt][1], a[mt][2], a[mt][3],
                            a_base + (uint32_t)mt * (16u * AS_STRIDE) + ka);
#pragma unroll
                for (int nt = 0; nt < 4; nt++)
                    LDSM_X2(b[nt][0], b[nt][1],
                            bb + (uint32_t)nt * (8u * BS_STRIDE) + (uint32_t)k16 * 32u);
#pragma unroll
                for (int mt = 0; mt < 4; mt++)
#pragma unroll
                    for (int nt = 0; nt < 4; nt++)
                        MMA16816(C[mt][nt], a[mt], b[nt]);
            }
            __syncthreads();
            if (kc + 2 < 8) {
                const __nv_bfloat16* bsrc = g_bbf + (size_t)code0 * DIM + (kc + 2) * 64;
#pragma unroll
                for (int u = 0; u < 4; u++) {
                    int i = tid + u * 256;
                    int code = i >> 3, ch = i & 7;
                    CP_ASYNC16(Bs + (uint32_t)(kc & 1) * BBUF + (uint32_t)code * BS_STRIDE + (uint32_t)ch * 16u,
                               bsrc + (size_t)code * DIM + ch * 8);
                }
                CP_COMMIT();
            }
        }

        // Epilogue: distances + candidate collection
#pragma unroll
        for (int mt = 0; mt < 4; mt++) {
#pragma unroll
            for (int nt = 0; nt < 4; nt++) {
                const int codeL = warp_n * 32 + nt * 8 + t4 * 2;
                const float c2a = c2p[codeL];
                const float c2b = c2p[codeL + 1];
#pragma unroll
                for (int h = 0; h < 2; h++) {
                    const int ri = mt * 2 + h;
                    const float d0 = __fadd_rn(__fadd_rn(x2v[ri],
                                        -__fmul_rn(2.0f, C[mt][nt][h * 2 + 0])), c2a);
                    const float d1 = __fadd_rn(__fadd_rn(x2v[ri],
                                        -__fmul_rn(2.0f, C[mt][nt][h * 2 + 1])), c2b);
                    float rm = runmin[ri];
                    if (d0 <= rm + MARGIN) {
                        int pos = atomicAdd(&g_cand_cnt[grow[ri]], 1);
                        if (pos < CAP) g_cand[grow[ri] * CAP + pos] = code0 + codeL;
                    }
                    if (d0 < rm) rm = d0;
                    if (d1 <= rm + MARGIN) {
                        int pos = atomicAdd(&g_cand_cnt[grow[ri]], 1);
                        if (pos < CAP) g_cand[grow[ri] * CAP + pos] = code0 + codeL + 1;
                    }
                    if (d1 < rm) rm = d1;
                    runmin[ri] = rm;
                }
            }
        }
    }
}

// ---------------------------------------------------------------------------
// Exact refine: bitwise round-3 chains (k-sequential fmaf) + exact epilogue +
// first-index tie-break. Sound full-scan fallback on counter overflow.
__global__ void refine_kernel(const float* __restrict__ X, const float* __restrict__ CB,
                              float* __restrict__ out, int out_size) {
    const int row  = blockIdx.x * 4 + (threadIdx.x >> 5);
    const int lane = threadIdx.x & 31;
    const float x2r = g_x2[row];
    const float* xr = X + (size_t)row * DIM;

    float bestd = 3.4e38f;
    int   besti = 0x7fffffff;
    const int cnt_raw = g_cand_cnt[row];

    if (cnt_raw > CAP || cnt_raw == 0) {
        for (int c0 = lane; c0 < KCODES; c0 += 64) {
            const int c1 = c0 + 32;
            const float* p0 = CB + (size_t)c0 * DIM;
            const float* p1 = CB + (size_t)c1 * DIM;
            float a0 = 0.f, a1 = 0.f;
            for (int k = 0; k < DIM; k++) {
                a0 = __fmaf_rn(xr[k], p0[k], a0);
                a1 = __fmaf_rn(xr[k], p1[k], a1);
            }
            float d0 = __fadd_rn(__fadd_rn(x2r, -__fmul_rn(2.0f, a0)), g_c2[c0]);
            float d1 = __fadd_rn(__fadd_rn(x2r, -__fmul_rn(2.0f, a1)), g_c2[c1]);
            if (d0 < bestd || (d0 == bestd && c0 < besti)) { bestd = d0; besti = c0; }
            if (d1 < bestd || (d1 == bestd && c1 < besti)) { bestd = d1; besti = c1; }
        }
    } else {
        for (int c = lane; c < cnt_raw; c += 32) {
            const int code = g_cand[row * CAP + c];
            const float* p = CB + (size_t)code * DIM;
            float acc = 0.f;
            for (int k = 0; k < DIM; k++) acc = __fmaf_rn(xr[k], p[k], acc);
            const float d = __fadd_rn(__fadd_rn(x2r, -__fmul_rn(2.0f, acc)), g_c2[code]);
            if (d < bestd || (d == bestd && code < besti)) { bestd = d; besti = code; }
        }
    }
#pragma unroll
    for (int o = 16; o; o >>= 1) {
        float ov = __shfl_xor_sync(0xFFFFFFFFu, bestd, o);
        int   oi = __shfl_xor_sync(0xFFFFFFFFu, besti, o);
        if (ov < bestd || (ov == bestd && oi < besti)) { bestd = ov; besti = oi; }
    }
    if (lane == 0) {
        g_idx[row] = besti;
        if (out_size >= NROWS * DIM + 1 + NROWS)
            out[NROWS * DIM + 1 + row] = (float)besti;
        else if (out_size == NROWS)
            out[row] = (float)besti;
    }
}

// ---------------------------------------------------------------------------
// Gather with STE rounding: out = fl(x + fl(q - x)); loss accumulation
__global__ void gather_kernel(const float* __restrict__ X,
                              const float* __restrict__ CB,
                              float* __restrict__ out, int out_size) {
    const int row  = (blockIdx.x * blockDim.x + threadIdx.x) >> 5;
    const int lane = threadIdx.x & 31;
    const int idx  = g_idx[row];
    const float4* cp = reinterpret_cast<const float4*>(CB + (size_t)idx * DIM);
    const float4* xp = reinterpret_cast<const float4*>(X  + (size_t)row * DIM);
    float4* op = reinterpret_cast<float4*>(out + (size_t)row * DIM);
    const bool write_q = (out_size >= NROWS * DIM);
    double s = 0.0;
#pragma unroll
    for (int q = 0; q < 4; q++) {
        float4 c = cp[lane + 32 * q];
        float4 x = xp[lane + 32 * q];
        if (write_q) {
            float4 o;
            o.x = __fadd_rn(x.x, __fsub_rn(c.x, x.x));
            o.y = __fadd_rn(x.y, __fsub_rn(c.y, x.y));
            o.z = __fadd_rn(x.z, __fsub_rn(c.z, x.z));
            o.w = __fadd_rn(x.w, __fsub_rn(c.w, x.w));
            op[lane + 32 * q] = o;
        }
        float dx = c.x - x.x, dy = c.y - x.y, dz = c.z - x.z, dw = c.w - x.w;
        s += (double)dx * dx + (double)dy * dy + (double)dz * dz + (double)dw * dw;
    }
#pragma unroll
    for (int o = 16; o; o >>= 1) s += __shfl_xor_sync(0xFFFFFFFFu, s, o);
    __shared__ double ss[8];
    if (lane == 0) ss[threadIdx.x >> 5] = s;
    __syncthreads();
    if (threadIdx.x == 0) {
        double tot = 0.0;
#pragma unroll
        for (int w = 0; w < 8; w++) tot += ss[w];
        atomicAdd(&g_loss, tot);
    }
}

__global__ void loss_kernel(float* __restrict__ out, int out_size) {
    if (out_size >= NROWS * DIM + 1)
        out[NROWS * DIM] = (float)(1.25 * g_loss / ((double)NROWS * (double)DIM));
    else if (out_size == 1)
        out[0] = (float)(1.25 * g_loss / ((double)NROWS * (double)DIM));
}

// ---------------------------------------------------------------------------
extern "C" void kernel_launch(void* const* d_in, const int* in_sizes, int n_in,
                              void* d_out, int out_size) {
    const float* X  = (const float*)d_in[0];
    const float* CB = (const float*)d_in[1];
    float* out = (float*)d_out;

    __nv_bfloat16 *abf, *bbf;
    cudaGetSymbolAddress((void**)&abf, g_abf);
    cudaGetSymbolAddress((void**)&bbf, g_bbf);

    cudaFuncSetAttribute(filter_kernel, cudaFuncAttributeMaxDynamicSharedMemorySize, SMEM_TOT);

    convert_kernel<<<(NROWS * DIM) / 512, 512>>>(X, abf, NROWS * DIM);
    convert_kernel<<<(KCODES * DIM) / 512, 512>>>(CB, bbf, KCODES * DIM);
    c2_kernel<<<KCODES / 8, 256>>>(CB);
    x2_kernel<<<NROWS / 256, 256>>>(X);
    {
        dim3 grid(NROWS / ROWT, 2);
        filter_kernel<<<grid, 256, SMEM_TOT>>>();
    }
    refine_kernel<<<NROWS / 4, 128>>>(X, CB, out, out_size);
    gather_kernel<<<NROWS / 8, 256>>>(X, CB, out, out_size);
    loss_kernel<<<1, 1>>>(out, out_size);
}

// round 7
// speedup vs baseline: 155.7783x; 155.7783x over previous
#include <cuda_runtime.h>
#include <cuda_bf16.h>
#include <cstdint>

#define NROWS  8192
#define DIM    512
#define KCODES 16384
#define CAP    256
#define MARGIN 8e-4f

// Filter-kernel geometry
#define ROWT      128                 // rows per CTA
#define AS_STRIDE 1040u               // bytes per A smem row (520 halves)
#define AS_BYTES  (128u * AS_STRIDE)  // 133120
#define BS_STRIDE 144u                // bytes per B smem row (72 halves)
#define BBUF      (128u * BS_STRIDE)  // 18432 per buffer
#define C2_OFF    (AS_BYTES + 2u * BBUF)          // 169984
#define RM_OFF    (C2_OFF + 512u)                 // per-row running min (128 ints)
#define SMEM_TOT  (RM_OFF + 512u)                 // 170    +1KB

// ---------------- device-global scratch (no runtime allocation) -------------
__device__ __nv_bfloat16 g_abf[NROWS * DIM];     // 8 MB
__device__ __nv_bfloat16 g_bbf[KCODES * DIM];    // 16 MB
__device__ float  g_c2[KCODES];
__device__ float  g_x2[NROWS];
__device__ int    g_cand_cnt[NROWS];
__device__ int    g_cand[NROWS * CAP];
__device__ int    g_idx[NROWS];
__device__ double g_loss;

// ---------------- PTX helpers ----------------------------------------------
static __device__ __forceinline__ uint32_t sptr(const void* p) {
    return (uint32_t)__cvta_generic_to_shared(p);
}
#define CP_ASYNC16(dst, src) \
    asm volatile("cp.async.cg.shared.global [%0], [%1], 16;" :: "r"(dst), "l"(src))
#define CP_COMMIT() asm volatile("cp.async.commit_group;")
#define CP_WAIT(n)  asm volatile("cp.async.wait_group %0;" :: "n"(n))

#define LDSM_X4(r0, r1, r2, r3, addr) \
    asm volatile("ldmatrix.sync.aligned.m8n8.x4.shared.b16 {%0,%1,%2,%3}, [%4];" \
        : "=r"(r0), "=r"(r1), "=r"(r2), "=r"(r3) : "r"(addr))
#define LDSM_X2(r0, r1, addr) \
    asm volatile("ldmatrix.sync.aligned.m8n8.x2.shared.b16 {%0,%1}, [%2];" \
        : "=r"(r0), "=r"(r1) : "r"(addr))
#define MMA16816(C, A, B) \
    asm volatile("mma.sync.aligned.m16n8k16.row.col.f32.bf16.bf16.f32 " \
        "{%0,%1,%2,%3}, {%4,%5,%6,%7}, {%8,%9}, {%0,%1,%2,%3};" \
        : "+f"((C)[0]), "+f"((C)[1]), "+f"((C)[2]), "+f"((C)[3]) \
        : "r"((A)[0]), "r"((A)[1]), "r"((A)[2]), "r"((A)[3]), "r"((B)[0]), "r"((B)[1]))

// ---------------------------------------------------------------------------
__global__ void convert_kernel(const float* __restrict__ in,
                               __nv_bfloat16* __restrict__ out, int total) {
    int idx = blockIdx.x * blockDim.x + threadIdx.x;
    if (idx < total) out[idx] = __float2bfloat16(in[idx]);
}

// ---------------------------------------------------------------------------
__global__ void c2_kernel(const float* __restrict__ cb) {
    const int row  = blockIdx.x * 8 + (threadIdx.x >> 5);
    const int lane = threadIdx.x & 31;
    const float4* p = reinterpret_cast<const float4*>(cb + (size_t)row * DIM);
    float s = 0.f;
#pragma unroll
    for (int q = 0; q < 4; q++) {
        float4 v = p[lane + 32 * q];
        s += v.x * v.x + v.y * v.y + v.z * v.z + v.w * v.w;
    }
#pragma unroll
    for (int o = 16; o; o >>= 1) s += __shfl_xor_sync(0xFFFFFFFFu, s, o);
    if (lane == 0) g_c2[row] = s;
}

// x2 strict sequential fp32 (reference rounding order); zeroes loss+counters
__global__ void x2_kernel(const float* __restrict__ x) {
    const int row = blockIdx.x * blockDim.x + threadIdx.x;
    if (row == 0) g_loss = 0.0;
    if (row >= NROWS) return;
    g_cand_cnt[row] = 0;
    const float4* p = reinterpret_cast<const float4*>(x + (size_t)row * DIM);
    float acc = 0.f;
#pragma unroll 8
    for (int i = 0; i < DIM / 4; i++) {
        float4 v = __ldg(p + i);
        acc = __fadd_rn(acc, __fmul_rn(v.x, v.x));
        acc = __fadd_rn(acc, __fmul_rn(v.y, v.y));
        acc = __fadd_rn(acc, __fmul_rn(v.z, v.z));
        acc = __fadd_rn(acc, __fmul_rn(v.w, v.w));
    }
    g_x2[row] = acc;
}

// ---------------------------------------------------------------------------
// bf16 HMMA filter: approximate distances + candidate collection against a
// SHARED per-row running min (s_rm), so collects/row stay far below CAP.
__global__ __launch_bounds__(256, 1)
void filter_kernel() {
    extern __shared__ char smem[];
    const uint32_t As = sptr(smem);
    const uint32_t Bs = As + AS_BYTES;
    float* c2p = reinterpret_cast<float*>(smem + C2_OFF);
    int*   s_rm = reinterpret_cast<int*>(smem + RM_OFF);   // 128 per-row minima

    const int tid    = threadIdx.x;
    const int lane   = tid & 31;
    const int wid    = tid >> 5;
    const int warp_m = wid >> 2;          // 0..1  (64 rows each)
    const int warp_n = wid & 3;           // 0..3  (32 codes each)
    const int rt     = blockIdx.x * ROWT;
    const int half   = blockIdx.y;        // 0..1
    const int g      = lane >> 2;         // group 0..7
    const int t4     = lane & 3;

    // ldmatrix lane address bases
    const int lr   = lane & 7;
    const int lsel = lane >> 3;                       // 0..3
    const uint32_t a_base = As + (uint32_t)(warp_m * 64 + (lsel & 1) * 8 + lr) * AS_STRIDE
                               + (uint32_t)((lsel >> 1) * 8) * 2u;
    const uint32_t b_base = Bs + (uint32_t)(warp_n * 32 + lr) * BS_STRIDE
                               + (uint32_t)((lsel & 1) * 8) * 2u;

    if (tid < 128) s_rm[tid] = 0x7f800000;   // +inf

    // Resident A load (one cp.async group)
    {
        const __nv_bfloat16* asrc = g_abf + (size_t)rt * DIM;
        for (int i = tid; i < 8192; i += 256) {
            int row = i >> 6, ch = i & 63;
            CP_ASYNC16(As + (uint32_t)row * AS_STRIDE + (uint32_t)ch * 16u,
                       asrc + (size_t)row * DIM + ch * 8);
        }
        CP_COMMIT();
        CP_WAIT(0);
        __syncthreads();
    }

    // per-lane row metadata (8 rows: mt 0..3 x h 0..1)
    int   grow[8], rowl[8];
    float x2v[8];
#pragma unroll
    for (int mt = 0; mt < 4; mt++)
#pragma unroll
        for (int h = 0; h < 2; h++) {
            int ri = mt * 2 + h;
            rowl[ri] = warp_m * 64 + mt * 16 + h * 8 + g;
            grow[ri] = rt + rowl[ri];
            x2v[ri]  = g_x2[grow[ri]];
        }

    for (int ct = 0; ct < 64; ct++) {
        const int code0 = half * 8192 + ct * 128;

        // issue B chunks kc=0,1
#pragma unroll
        for (int kc = 0; kc < 2; kc++) {
            const __nv_bfloat16* bsrc = g_bbf + (size_t)code0 * DIM + kc * 64;
#pragma unroll
            for (int u = 0; u < 4; u++) {
                int i = tid + u * 256;
                int code = i >> 3, ch = i & 7;
                CP_ASYNC16(Bs + (uint32_t)kc * BBUF + (uint32_t)code * BS_STRIDE + (uint32_t)ch * 16u,
                           bsrc + (size_t)code * DIM + ch * 8);
            }
            CP_COMMIT();
        }
        __syncthreads();   // prior epilogue done reading c2p/s_rm
        if (tid < 128) c2p[tid] = g_c2[code0 + tid];

        float C[4][4][4];
#pragma unroll
        for (int mt = 0; mt < 4; mt++)
#pragma unroll
            for (int nt = 0; nt < 4; nt++)
#pragma unroll
                for (int e = 0; e < 4; e++) C[mt][nt][e] = 0.f;

        for (int kc = 0; kc < 8; kc++) {
            if (kc < 7) { CP_WAIT(1); } else { CP_WAIT(0); }
            __syncthreads();
            const uint32_t bb = b_base + (uint32_t)(kc & 1) * BBUF;
#pragma unroll
            for (int k16 = 0; k16 < 4; k16++) {
                const uint32_t ka = (uint32_t)(kc * 64 + k16 * 16) * 2u;
                uint32_t a[4][4], b[4][2];
#pragma unroll
                for (int mt = 0; mt < 4; mt++)
                    LDSM_X4(a[mt][0], a[mt][1], a[mt][2], a[mt][3],
                            a_base + (uint32_t)mt * (16u * AS_STRIDE) + ka);
#pragma unroll
                for (int nt = 0; nt < 4; nt++)
                    LDSM_X2(b[nt][0], b[nt][1],
                            bb + (uint32_t)nt * (8u * BS_STRIDE) + (uint32_t)k16 * 32u);
#pragma unroll
                for (int mt = 0; mt < 4; mt++)
#pragma unroll
                    for (int nt = 0; nt < 4; nt++)
                        MMA16816(C[mt][nt], a[mt], b[nt]);
            }
            __syncthreads();
            if (kc + 2 < 8) {
                const __nv_bfloat16* bsrc = g_bbf + (size_t)code0 * DIM + (kc + 2) * 64;
#pragma unroll
                for (int u = 0; u < 4; u++) {
                    int i = tid + u * 256;
                    int code = i >> 3, ch = i & 7;
                    CP_ASYNC16(Bs + (uint32_t)(kc & 1) * BBUF + (uint32_t)code * BS_STRIDE + (uint32_t)ch * 16u,
                               bsrc + (size_t)code * DIM + ch * 8);
                }
                CP_COMMIT();
            }
        }

        // Epilogue 1: distances in-place into C; per-row tile-local min
        float locmin[8];
#pragma unroll
        for (int ri = 0; ri < 8; ri++) locmin[ri] = 3.4e38f;
#pragma unroll
        for (int mt = 0; mt < 4; mt++) {
#pragma unroll
            for (int nt = 0; nt < 4; nt++) {
                const int codeL = warp_n * 32 + nt * 8 + t4 * 2;
                const float c2a = c2p[codeL];
                const float c2b = c2p[codeL + 1];
#pragma unroll
                for (int h = 0; h < 2; h++) {
                    const int ri = mt * 2 + h;
                    const float d0 = __fadd_rn(__fadd_rn(x2v[ri],
                                        -__fmul_rn(2.0f, C[mt][nt][h * 2 + 0])), c2a);
                    const float d1 = __fadd_rn(__fadd_rn(x2v[ri],
                                        -__fmul_rn(2.0f, C[mt][nt][h * 2 + 1])), c2b);
                    C[mt][nt][h * 2 + 0] = d0;
                    C[mt][nt][h * 2 + 1] = d1;
                    float m = d0 < d1 ? d0 : d1;
                    if (m < locmin[ri]) locmin[ri] = m;
                }
            }
        }
        // Epilogue 2: publish mins (distances positive -> int order == float order)
#pragma unroll
        for (int ri = 0; ri < 8; ri++)
            atomicMin(&s_rm[rowl[ri]], __float_as_int(locmin[ri]));
        __syncthreads();
        // Epilogue 3: collect with global-row threshold (lagged => superset, sound)
        float thr[8];
#pragma unroll
        for (int ri = 0; ri < 8; ri++)
            thr[ri] = __int_as_float(s_rm[rowl[ri]]) + MARGIN;
#pragma unroll
        for (int mt = 0; mt < 4; mt++) {
#pragma unroll
            for (int nt = 0; nt < 4; nt++) {
                const int codeL = warp_n * 32 + nt * 8 + t4 * 2;
#pragma unroll
                for (int h = 0; h < 2; h++) {
                    const int ri = mt * 2 + h;
                    if (C[mt][nt][h * 2 + 0] <= thr[ri]) {
                        int pos = atomicAdd(&g_cand_cnt[grow[ri]], 1);
                        if (pos < CAP) g_cand[grow[ri] * CAP + pos] = code0 + codeL;
                    }
                    if (C[mt][nt][h * 2 + 1] <= thr[ri]) {
                        int pos = atomicAdd(&g_cand_cnt[grow[ri]], 1);
                        if (pos < CAP) g_cand[grow[ri] * CAP + pos] = code0 + codeL + 1;
                    }
                }
            }
        }
    }
}

// ---------------------------------------------------------------------------
// Exact refine: bitwise round-3 chains (k-sequential fmaf) + exact epilogue +
// first-index tie-break. Sound full-scan fallback on counter overflow.
__global__ void refine_kernel(const float* __restrict__ X, const float* __restrict__ CB,
                              float* __restrict__ out, int out_size) {
    const int row  = blockIdx.x * 4 + (threadIdx.x >> 5);
    const int lane = threadIdx.x & 31;
    const float x2r = g_x2[row];
    const float* xr = X + (size_t)row * DIM;

    float bestd = 3.4e38f;
    int   besti = 0x7fffffff;
    const int cnt_raw = g_cand_cnt[row];

    if (cnt_raw > CAP || cnt_raw == 0) {
        for (int c0 = lane; c0 < KCODES; c0 += 64) {
            const int c1 = c0 + 32;
            const float* p0 = CB + (size_t)c0 * DIM;
            const float* p1 = CB + (size_t)c1 * DIM;
            float a0 = 0.f, a1 = 0.f;
            for (int k = 0; k < DIM; k++) {
                a0 = __fmaf_rn(xr[k], p0[k], a0);
                a1 = __fmaf_rn(xr[k], p1[k], a1);
            }
            float d0 = __fadd_rn(__fadd_rn(x2r, -__fmul_rn(2.0f, a0)), g_c2[c0]);
            float d1 = __fadd_rn(__fadd_rn(x2r, -__fmul_rn(2.0f, a1)), g_c2[c1]);
            if (d0 < bestd || (d0 == bestd && c0 < besti)) { bestd = d0; besti = c0; }
            if (d1 < bestd || (d1 == bestd && c1 < besti)) { bestd = d1; besti = c1; }
        }
    } else {
        for (int c = lane; c < cnt_raw; c += 32) {
            const int code = g_cand[row * CAP + c];
            const float* p = CB + (size_t)code * DIM;
            float acc = 0.f;
            for (int k = 0; k < DIM; k++) acc = __fmaf_rn(xr[k], p[k], acc);
            const float d = __fadd_rn(__fadd_rn(x2r, -__fmul_rn(2.0f, acc)), g_c2[code]);
            if (d < bestd || (d == bestd && code < besti)) { bestd = d; besti = code; }
        }
    }
#pragma unroll
    for (int o = 16; o; o >>= 1) {
        float ov = __shfl_xor_sync(0xFFFFFFFFu, bestd, o);
        int   oi = __shfl_xor_sync(0xFFFFFFFFu, besti, o);
        if (ov < bestd || (ov == bestd && oi < besti)) { bestd = ov; besti = oi; }
    }
    if (lane == 0) {
        g_idx[row] = besti;
        if (out_size >= NROWS * DIM + 1 + NROWS)
            out[NROWS * DIM + 1 + row] = (float)besti;
        else if (out_size == NROWS)
            out[row] = (float)besti;
    }
}

// ---------------------------------------------------------------------------
// Gather with STE rounding: out = fl(x + fl(q - x)); loss accumulation
__global__ void gather_kernel(const float* __restrict__ X,
                              const float* __restrict__ CB,
                              float* __restrict__ out, int out_size) {
    const int row  = (blockIdx.x * blockDim.x + threadIdx.x) >> 5;
    const int lane = threadIdx.x & 31;
    const int idx  = g_idx[row];
    const float4* cp = reinterpret_cast<const float4*>(CB + (size_t)idx * DIM);
    const float4* xp = reinterpret_cast<const float4*>(X  + (size_t)row * DIM);
    float4* op = reinterpret_cast<float4*>(out + (size_t)row * DIM);
    const bool write_q = (out_size >= NROWS * DIM);
    double s = 0.0;
#pragma unroll
    for (int q = 0; q < 4; q++) {
        float4 c = cp[lane + 32 * q];
        float4 x = xp[lane + 32 * q];
        if (write_q) {
            float4 o;
            o.x = __fadd_rn(x.x, __fsub_rn(c.x, x.x));
            o.y = __fadd_rn(x.y, __fsub_rn(c.y, x.y));
            o.z = __fadd_rn(x.z, __fsub_rn(c.z, x.z));
            o.w = __fadd_rn(x.w, __fsub_rn(c.w, x.w));
            op[lane + 32 * q] = o;
        }
        float dx = c.x - x.x, dy = c.y - x.y, dz = c.z - x.z, dw = c.w - x.w;
        s += (double)dx * dx + (double)dy * dy + (double)dz * dz + (double)dw * dw;
    }
#pragma unroll
    for (int o = 16; o; o >>= 1) s += __shfl_xor_sync(0xFFFFFFFFu, s, o);
    __shared__ double ss[8];
    if (lane == 0) ss[threadIdx.x >> 5] = s;
    __syncthreads();
    if (threadIdx.x == 0) {
        double tot = 0.0;
#pragma unroll
        for (int w = 0; w < 8; w++) tot += ss[w];
        atomicAdd(&g_loss, tot);
    }
}

__global__ void loss_kernel(float* __restrict__ out, int out_size) {
    if (out_size >= NROWS * DIM + 1)
        out[NROWS * DIM] = (float)(1.25 * g_loss / ((double)NROWS * (double)DIM));
    else if (out_size == 1)
        out[0] = (float)(1.25 * g_loss / ((double)NROWS * (double)DIM));
}

// ---------------------------------------------------------------------------
extern "C" void kernel_launch(void* const* d_in, const int* in_sizes, int n_in,
                              void* d_out, int out_size) {
    const float* X  = (const float*)d_in[0];
    const float* CB = (const float*)d_in[1];
    float* out = (float*)d_out;

    __nv_bfloat16 *abf, *bbf;
    cudaGetSymbolAddress((void**)&abf, g_abf);
    cudaGetSymbolAddress((void**)&bbf, g_bbf);

    cudaFuncSetAttribute(filter_kernel, cudaFuncAttributeMaxDynamicSharedMemorySize, SMEM_TOT);

    convert_kernel<<<(NROWS * DIM) / 512, 512>>>(X, abf, NROWS * DIM);
    convert_kernel<<<(KCODES * DIM) / 512, 512>>>(CB, bbf, KCODES * DIM);
    c2_kernel<<<KCODES / 8, 256>>>(CB);
    x2_kernel<<<NROWS / 256, 256>>>(X);
    {
        dim3 grid(NROWS / ROWT, 2);
        filter_kernel<<<grid, 256, SMEM_TOT>>>();
    }
    refine_kernel<<<NROWS / 4, 128>>>(X, CB, out, out_size);
    gather_kernel<<<NROWS / 8, 256>>>(X, CB, out, out_size);
    loss_kernel<<<1, 1>>>(out, out_size);
}

// round 8
// speedup vs baseline: 165.1627x; 1.0602x over previous
#include <cuda_runtime.h>
#include <cuda_bf16.h>
#include <cstdint>

#define NROWS  8192
#define DIM    512
#define KCODES 16384
#define CAP    256
#define MARGIN 8e-4f

// Filter-kernel geometry
#define ROWT      128                 // rows per CTA
#define AS_STRIDE 1040u               // bytes per A smem row (520 halves)
#define AS_BYTES  (128u * AS_STRIDE)  // 133120
#define BS_STRIDE 144u                // bytes per B smem row (72 halves)
#define BBUF      (128u * BS_STRIDE)  // 18432 per buffer
#define NBUF      4
#define C2_OFF    (AS_BYTES + NBUF * BBUF)        // 206848
#define RM_OFF    (C2_OFF + 512u)
#define SMEM_TOT  (RM_OFF + 512u)                 // 207872
#define NQ        512                 // total k-chunks per CTA (64 tiles x 8)

// ---------------- device-global scratch (no runtime allocation) -------------
__device__ __nv_bfloat16 g_abf[NROWS * DIM];     // 8 MB
__device__ __nv_bfloat16 g_bbf[KCODES * DIM];    // 16 MB
__device__ float  g_c2[KCODES];
__device__ float  g_x2[NROWS];
__device__ int    g_cand_cnt[NROWS];
__device__ int    g_cand[NROWS * CAP];
__device__ int    g_idx[NROWS];
__device__ double g_loss;

// ---------------- PTX helpers ----------------------------------------------
static __device__ __forceinline__ uint32_t sptr(const void* p) {
    return (uint32_t)__cvta_generic_to_shared(p);
}
#define CP_ASYNC16(dst, src) \
    asm volatile("cp.async.cg.shared.global [%0], [%1], 16;" :: "r"(dst), "l"(src))
#define CP_COMMIT() asm volatile("cp.async.commit_group;")
#define CP_WAIT(n)  asm volatile("cp.async.wait_group %0;" :: "n"(n))

#define LDSM_X4(r0, r1, r2, r3, addr) \
    asm volatile("ldmatrix.sync.aligned.m8n8.x4.shared.b16 {%0,%1,%2,%3}, [%4];" \
        : "=r"(r0), "=r"(r1), "=r"(r2), "=r"(r3) : "r"(addr))
#define LDSM_X2(r0, r1, addr) \
    asm volatile("ldmatrix.sync.aligned.m8n8.x2.shared.b16 {%0,%1}, [%2];" \
        : "=r"(r0), "=r"(r1) : "r"(addr))
#define MMA16816(C, A, B) \
    asm volatile("mma.sync.aligned.m16n8k16.row.col.f32.bf16.bf16.f32 " \
        "{%0,%1,%2,%3}, {%4,%5,%6,%7}, {%8,%9}, {%0,%1,%2,%3};" \
        : "+f"((C)[0]), "+f"((C)[1]), "+f"((C)[2]), "+f"((C)[3]) \
        : "r"((A)[0]), "r"((A)[1]), "r"((A)[2]), "r"((A)[3]), "r"((B)[0]), "r"((B)[1]))

// ---------------------------------------------------------------------------
// Vectorized fp32 -> bf16 convert (float4 in, 2x bf16x2 out)
__global__ void convert_kernel(const float4* __restrict__ in,
                               __nv_bfloat162* __restrict__ out, int total4) {
    int idx = blockIdx.x * blockDim.x + threadIdx.x;
    if (idx >= total4) return;
    float4 v = in[idx];
    out[idx * 2 + 0] = __floats2bfloat162_rn(v.x, v.y);
    out[idx * 2 + 1] = __floats2bfloat162_rn(v.z, v.w);
}

// ---------------------------------------------------------------------------
__global__ void c2_kernel(const float* __restrict__ cb) {
    const int row  = blockIdx.x * 8 + (threadIdx.x >> 5);
    const int lane = threadIdx.x & 31;
    const float4* p = reinterpret_cast<const float4*>(cb + (size_t)row * DIM);
    float s = 0.f;
#pragma unroll
    for (int q = 0; q < 4; q++) {
        float4 v = p[lane + 32 * q];
        s += v.x * v.x + v.y * v.y + v.z * v.z + v.w * v.w;
    }
#pragma unroll
    for (int o = 16; o; o >>= 1) s += __shfl_xor_sync(0xFFFFFFFFu, s, o);
    if (lane == 0) g_c2[row] = s;
}

// x2 strict sequential fp32 (reference rounding order); zeroes loss+counters.
// 32-thread blocks x 256 so all SMs participate (was 12% occupancy).
__global__ void x2_kernel(const float* __restrict__ x) {
    const int row = blockIdx.x * blockDim.x + threadIdx.x;
    if (row == 0) g_loss = 0.0;
    if (row >= NROWS) return;
    g_cand_cnt[row] = 0;
    const float4* p = reinterpret_cast<const float4*>(x + (size_t)row * DIM);
    float acc = 0.f;
#pragma unroll 8
    for (int i = 0; i < DIM / 4; i++) {
        float4 v = __ldg(p + i);
        acc = __fadd_rn(acc, __fmul_rn(v.x, v.x));
        acc = __fadd_rn(acc, __fmul_rn(v.y, v.y));
        acc = __fadd_rn(acc, __fmul_rn(v.z, v.z));
        acc = __fadd_rn(acc, __fmul_rn(v.w, v.w));
    }
    g_x2[row] = acc;
}

// ---------------------------------------------------------------------------
// bf16 HMMA filter, 16 warps, continuous 4-deep cp.async pipeline over all
// 512 k-chunks (no per-tile drain), one __syncthreads per chunk.
__global__ __launch_bounds__(512, 1)
void filter_kernel() {
    extern __shared__ char smem[];
    const uint32_t As = sptr(smem);
    const uint32_t Bs = As + AS_BYTES;
    float* c2p  = reinterpret_cast<float*>(smem + C2_OFF);
    int*   s_rm = reinterpret_cast<int*>(smem + RM_OFF);

    const int tid    = threadIdx.x;
    const int lane   = tid & 31;
    const int wid    = tid >> 5;          // 0..15
    const int warp_m = wid >> 2;          // 0..3  (32 rows each)
    const int warp_n = wid & 3;           // 0..3  (32 codes each)
    const int rt     = blockIdx.x * ROWT;
    const int half   = blockIdx.y;        // 0..1
    const int cbase  = half * 8192;
    const int g      = lane >> 2;
    const int t4     = lane & 3;

    const int lr   = lane & 7;
    const int lsel = lane >> 3;
    const uint32_t a_base = As + (uint32_t)(warp_m * 32 + (lsel & 1) * 8 + lr) * AS_STRIDE
                               + (uint32_t)((lsel >> 1) * 8) * 2u;
    const uint32_t b_lane = (uint32_t)(warp_n * 32 + lr) * BS_STRIDE
                          + (uint32_t)((lsel & 1) * 8) * 2u;

    if (tid < 128) s_rm[tid] = 0x7f800000;   // +inf

    // Resident A load
    {
        const __nv_bfloat16* asrc = g_abf + (size_t)rt * DIM;
        for (int i = tid; i < 8192; i += 512) {
            int row = i >> 6, ch = i & 63;
            CP_ASYNC16(As + (uint32_t)row * AS_STRIDE + (uint32_t)ch * 16u,
                       asrc + (size_t)row * DIM + ch * 8);
        }
        CP_COMMIT();
        CP_WAIT(0);
        __syncthreads();
    }

    // per-lane row metadata (4 rows: mt 0..1 x h 0..1)
    int   grow[4], rowl[4];
    float x2v[4];
#pragma unroll
    for (int mt = 0; mt < 2; mt++)
#pragma unroll
        for (int h = 0; h < 2; h++) {
            int ri = mt * 2 + h;
            rowl[ri] = warp_m * 32 + mt * 16 + h * 8 + g;
            grow[ri] = rt + rowl[ri];
            x2v[ri]  = g_x2[grow[ri]];
        }

    // B chunk issue: chunk q covers codes [cbase+(q>>3)*128, +128), k [(q&7)*64, +64)
    auto issue = [&](int q) {
        const int tile = q >> 3, kc = q & 7;
        const __nv_bfloat16* bsrc = g_bbf + (size_t)(cbase + tile * 128) * DIM + kc * 64;
        const uint32_t dstb = Bs + (uint32_t)(q & (NBUF - 1)) * BBUF;
#pragma unroll
        for (int u = 0; u < 2; u++) {
            int i = tid + u * 512;
            int code = i >> 3, ch = i & 7;
            CP_ASYNC16(dstb + (uint32_t)code * BS_STRIDE + (uint32_t)ch * 16u,
                       bsrc + (size_t)code * DIM + ch * 8);
        }
        CP_COMMIT();
    };

    issue(0); issue(1); issue(2);

    float C[2][4][4];

    for (int q = 0; q < NQ; q++) {
        if (q < NQ - 2)      { CP_WAIT(2); }
        else if (q == NQ - 2) { CP_WAIT(1); }
        else                  { CP_WAIT(0); }
        __syncthreads();

        if ((q & 7) == 0) {
            if (tid < 128) c2p[tid] = g_c2[cbase + (q >> 3) * 128 + tid];
#pragma unroll
            for (int mt = 0; mt < 2; mt++)
#pragma unroll
                for (int nt = 0; nt < 4; nt++)
#pragma unroll
                    for (int e = 0; e < 4; e++) C[mt][nt][e] = 0.f;
        }

        const uint32_t bb = Bs + (uint32_t)(q & (NBUF - 1)) * BBUF + b_lane;
#pragma unroll
        for (int k16 = 0; k16 < 4; k16++) {
            const uint32_t ka = (uint32_t)((q & 7) * 64 + k16 * 16) * 2u;
            uint32_t a[2][4], b[4][2];
#pragma unroll
            for (int mt = 0; mt < 2; mt++)
                LDSM_X4(a[mt][0], a[mt][1], a[mt][2], a[mt][3],
                        a_base + (uint32_t)mt * (16u * AS_STRIDE) + ka);
#pragma unroll
            for (int nt = 0; nt < 4; nt++)
                LDSM_X2(b[nt][0], b[nt][1],
                        bb + (uint32_t)nt * (8u * BS_STRIDE) + (uint32_t)k16 * 32u);
#pragma unroll
            for (int mt = 0; mt < 2; mt++)
#pragma unroll
                for (int nt = 0; nt < 4; nt++)
                    MMA16816(C[mt][nt], a[mt], b[nt]);
        }

        if (q + 3 < NQ) issue(q + 3);

        if ((q & 7) == 7) {
            const int code0 = cbase + (q >> 3) * 128;
            // Epilogue 1: distances + per-row local min
            float locmin[4];
#pragma unroll
            for (int ri = 0; ri < 4; ri++) locmin[ri] = 3.4e38f;
#pragma unroll
            for (int mt = 0; mt < 2; mt++) {
#pragma unroll
                for (int nt = 0; nt < 4; nt++) {
                    const int codeL = warp_n * 32 + nt * 8 + t4 * 2;
                    const float c2a = c2p[codeL];
                    const float c2b = c2p[codeL + 1];
#pragma unroll
                    for (int h = 0; h < 2; h++) {
                        const int ri = mt * 2 + h;
                        const float d0 = __fadd_rn(__fadd_rn(x2v[ri],
                                            -__fmul_rn(2.0f, C[mt][nt][h * 2 + 0])), c2a);
                        const float d1 = __fadd_rn(__fadd_rn(x2v[ri],
                                            -__fmul_rn(2.0f, C[mt][nt][h * 2 + 1])), c2b);
                        C[mt][nt][h * 2 + 0] = d0;
                        C[mt][nt][h * 2 + 1] = d1;
                        float m = d0 < d1 ? d0 : d1;
                        if (m < locmin[ri]) locmin[ri] = m;
                    }
                }
            }
            // Epilogue 2: publish (positive floats: int order == float order)
#pragma unroll
            for (int ri = 0; ri < 4; ri++)
                atomicMin(&s_rm[rowl[ri]], __float_as_int(locmin[ri]));
            __syncthreads();
            // Epilogue 3: collect (lagged global min => superset, sound)
            float thr[4];
#pragma unroll
            for (int ri = 0; ri < 4; ri++)
                thr[ri] = __int_as_float(s_rm[rowl[ri]]) + MARGIN;
#pragma unroll
            for (int mt = 0; mt < 2; mt++) {
#pragma unroll
                for (int nt = 0; nt < 4; nt++) {
                    const int codeL = warp_n * 32 + nt * 8 + t4 * 2;
#pragma unroll
                    for (int h = 0; h < 2; h++) {
                        const int ri = mt * 2 + h;
                        if (C[mt][nt][h * 2 + 0] <= thr[ri]) {
                            int pos = atomicAdd(&g_cand_cnt[grow[ri]], 1);
                            if (pos < CAP) g_cand[grow[ri] * CAP + pos] = code0 + codeL;
                        }
                        if (C[mt][nt][h * 2 + 1] <= thr[ri]) {
                            int pos = atomicAdd(&g_cand_cnt[grow[ri]], 1);
                            if (pos < CAP) g_cand[grow[ri] * CAP + pos] = code0 + codeL + 1;
                        }
                    }
                }
            }
        }
    }
}

// ---------------------------------------------------------------------------
// Exact refine: bitwise round-3 chains (k-sequential fmaf) + exact epilogue +
// first-index tie-break. Sound full-scan fallback on counter overflow.
__global__ void refine_kernel(const float* __restrict__ X, const float* __restrict__ CB,
                              float* __restrict__ out, int out_size) {
    const int row  = blockIdx.x * 4 + (threadIdx.x >> 5);
    const int lane = threadIdx.x & 31;
    const float x2r = g_x2[row];
    const float* xr = X + (size_t)row * DIM;

    float bestd = 3.4e38f;
    int   besti = 0x7fffffff;
    const int cnt_raw = g_cand_cnt[row];

    if (cnt_raw > CAP || cnt_raw == 0) {
        for (int c0 = lane; c0 < KCODES; c0 += 64) {
            const int c1 = c0 + 32;
            const float* p0 = CB + (size_t)c0 * DIM;
            const float* p1 = CB + (size_t)c1 * DIM;
            float a0 = 0.f, a1 = 0.f;
            for (int k = 0; k < DIM; k++) {
                a0 = __fmaf_rn(xr[k], p0[k], a0);
                a1 = __fmaf_rn(xr[k], p1[k], a1);
            }
            float d0 = __fadd_rn(__fadd_rn(x2r, -__fmul_rn(2.0f, a0)), g_c2[c0]);
            float d1 = __fadd_rn(__fadd_rn(x2r, -__fmul_rn(2.0f, a1)), g_c2[c1]);
            if (d0 < bestd || (d0 == bestd && c0 < besti)) { bestd = d0; besti = c0; }
            if (d1 < bestd || (d1 == bestd && c1 < besti)) { bestd = d1; besti = c1; }
        }
    } else {
        for (int c = lane; c < cnt_raw; c += 32) {
            const int code = g_cand[row * CAP + c];
            const float* p = CB + (size_t)code * DIM;
            float acc = 0.f;
            for (int k = 0; k < DIM; k++) acc = __fmaf_rn(xr[k], p[k], acc);
            const float d = __fadd_rn(__fadd_rn(x2r, -__fmul_rn(2.0f, acc)), g_c2[code]);
            if (d < bestd || (d == bestd && code < besti)) { bestd = d; besti = code; }
        }
    }
#pragma unroll
    for (int o = 16; o; o >>= 1) {
        float ov = __shfl_xor_sync(0xFFFFFFFFu, bestd, o);
        int   oi = __shfl_xor_sync(0xFFFFFFFFu, besti, o);
        if (ov < bestd || (ov == bestd && oi < besti)) { bestd = ov; besti = oi; }
    }
    if (lane == 0) {
        g_idx[row] = besti;
        if (out_size >= NROWS * DIM + 1 + NROWS)
            out[NROWS * DIM + 1 + row] = (float)besti;
        else if (out_size == NROWS)
            out[row] = (float)besti;
    }
}

// ---------------------------------------------------------------------------
// Gather with STE rounding: out = fl(x + fl(q - x)); loss accumulation
__global__ void gather_kernel(const float* __restrict__ X,
                              const float* __restrict__ CB,
                              float* __restrict__ out, int out_size) {
    const int row  = (blockIdx.x * blockDim.x + threadIdx.x) >> 5;
    const int lane = threadIdx.x & 31;
    const int idx  = g_idx[row];
    const float4* cp = reinterpret_cast<const float4*>(CB + (size_t)idx * DIM);
    const float4* xp = reinterpret_cast<const float4*>(X  + (size_t)row * DIM);
    float4* op = reinterpret_cast<float4*>(out + (size_t)row * DIM);
    const bool write_q = (out_size >= NROWS * DIM);
    double s = 0.0;
#pragma unroll
    for (int q = 0; q < 4; q++) {
        float4 c = cp[lane + 32 * q];
        float4 x = xp[lane + 32 * q];
        if (write_q) {
            float4 o;
            o.x = __fadd_rn(x.x, __fsub_rn(c.x, x.x));
            o.y = __fadd_rn(x.y, __fsub_rn(c.y, x.y));
            o.z = __fadd_rn(x.z, __fsub_rn(c.z, x.z));
            o.w = __fadd_rn(x.w, __fsub_rn(c.w, x.w));
            op[lane + 32 * q] = o;
        }
        float dx = c.x - x.x, dy = c.y - x.y, dz = c.z - x.z, dw = c.w - x.w;
        s += (double)dx * dx + (double)dy * dy + (double)dz * dz + (double)dw * dw;
    }
#pragma unroll
    for (int o = 16; o; o >>= 1) s += __shfl_xor_sync(0xFFFFFFFFu, s, o);
    __shared__ double ss[8];
    if (lane == 0) ss[threadIdx.x >> 5] = s;
    __syncthreads();
    if (threadIdx.x == 0) {
        double tot = 0.0;
#pragma unroll
        for (int w = 0; w < 8; w++) tot += ss[w];
        atomicAdd(&g_loss, tot);
    }
}

__global__ void loss_kernel(float* __restrict__ out, int out_size) {
    if (out_size >= NROWS * DIM + 1)
        out[NROWS * DIM] = (float)(1.25 * g_loss / ((double)NROWS * (double)DIM));
    else if (out_size == 1)
        out[0] = (float)(1.25 * g_loss / ((double)NROWS * (double)DIM));
}

// ---------------------------------------------------------------------------
extern "C" void kernel_launch(void* const* d_in, const int* in_sizes, int n_in,
                              void* d_out, int out_size) {
    const float* X  = (const float*)d_in[0];
    const float* CB = (const float*)d_in[1];
    float* out = (float*)d_out;

    __nv_bfloat16 *abf, *bbf;
    cudaGetSymbolAddress((void**)&abf, g_abf);
    cudaGetSymbolAddress((void**)&bbf, g_bbf);

    cudaFuncSetAttribute(filter_kernel, cudaFuncAttributeMaxDynamicSharedMemorySize, SMEM_TOT);

    convert_kernel<<<(NROWS * DIM / 4) / 256, 256>>>(
        (const float4*)X, (__nv_bfloat162*)abf, NROWS * DIM / 4);
    convert_kernel<<<(KCODES * DIM / 4) / 256, 256>>>(
        (const float4*)CB, (__nv_bfloat162*)bbf, KCODES * DIM / 4);
    c2_kernel<<<KCODES / 8, 256>>>(CB);
    x2_kernel<<<NROWS / 32, 32>>>(X);
    {
        dim3 grid(NROWS / ROWT, 2);
        filter_kernel<<<grid, 512, SMEM_TOT>>>();
    }
    refine_kernel<<<NROWS / 4, 128>>>(X, CB, out, out_size);
    gather_kernel<<<NROWS / 8, 256>>>(X, CB, out, out_size);
    loss_kernel<<<1, 1>>>(out, out_size);
}